// round 1
// baseline (speedup 1.0000x reference)
#include <cuda_runtime.h>

// ---------------------------------------------------------------------------
// edge_aggregation: B=4, E=8000, N=2000, D=256, HID=128, T=5
//
//   edges = H @ ori                                  [B,E,D]
//   for t: h = relu(edges@W1[t]+b1[t]); y = h@W2[t]+b2[t]
//   ef    = sum_t edge_distribution[...,t] * y       [B,E,D]
//   out   = concat(H^T @ ef, ori)                    [B,N,2D]
//
// Round 1: fp32 tiled SGEMM (128x128x8, 8x8 microtile, 256 threads).
// ---------------------------------------------------------------------------

#define BM 128
#define BN 128
#define BK 8
#define TM 8
#define TN 8

// scratch (allocation-free rule: __device__ globals)
__device__ float g_edges[4 * 8000 * 256];   // 32.8 MB
__device__ float g_h[4 * 8000 * 128];       // 16.4 MB
__device__ float g_ef[4 * 8000 * 256];      // 32.8 MB

// EPI: 0 = C = acc
//      1 = C = relu(acc + bias[col])
//      2 = C (init ? = : +=) gate[row*gate_ld+gate_idx] * (acc + bias[col])
// TRANS_A: false -> A is [M,K] row-major (lda = K-ish row length)
//          true  -> A is [K,M] row-major (lda = M-ish row length)
// Assumes: N % BN == 0, K % BK == 0, K % 4 == 0 (true for all uses here).
template <int EPI, bool TRANS_A>
__global__ __launch_bounds__(256)
void sgemm_kernel(const float* __restrict__ A, const float* __restrict__ B,
                  float* __restrict__ C,
                  int M, int N, int K,
                  long sA, long sB, long sC,
                  int lda, int ldb, int ldc,
                  const float* __restrict__ bias,
                  const float* __restrict__ gate,
                  int gate_idx, int gate_ld, int init_flag)
{
    __shared__ float As[BK][BM];
    __shared__ float Bs[BK][BN];

    const int z = blockIdx.z;
    A += (long)z * sA;
    B += (long)z * sB;
    C += (long)z * sC;

    const int m0 = blockIdx.x * BM;
    const int n0 = blockIdx.y * BN;
    const int tid = threadIdx.x;
    const int tx = tid & 15;   // 16 cols of threads
    const int ty = tid >> 4;   // 16 rows of threads

    float acc[TM][TN];
#pragma unroll
    for (int i = 0; i < TM; i++)
#pragma unroll
        for (int j = 0; j < TN; j++) acc[i][j] = 0.f;

    // B-tile (and TN A-tile) loader indices: [BK rows][BN cols], float4 per thread
    const int b_r = tid >> 5;          // 0..7
    const int b_c = (tid & 31) << 2;   // 0..124
    // NN A-tile loader: [BM rows][BK cols], float4 along K
    const int a_r = tid >> 1;          // 0..127
    const int a_c = (tid & 1) << 2;    // 0 or 4

    for (int k0 = 0; k0 < K; k0 += BK) {
        if constexpr (!TRANS_A) {
            const int gm = m0 + a_r;
            float4 v = make_float4(0.f, 0.f, 0.f, 0.f);
            if (gm < M) v = *(const float4*)(A + (long)gm * lda + (k0 + a_c));
            As[a_c + 0][a_r] = v.x;
            As[a_c + 1][a_r] = v.y;
            As[a_c + 2][a_r] = v.z;
            As[a_c + 3][a_r] = v.w;
        } else {
            const int gk = k0 + b_r;
            const int gm = m0 + b_c;
            const float* src = A + (long)gk * lda + gm;
            if (gm + 3 < M) {
                *(float4*)&As[b_r][b_c] = *(const float4*)src;
            } else {
#pragma unroll
                for (int u = 0; u < 4; u++)
                    As[b_r][b_c + u] = (gm + u < M) ? src[u] : 0.f;
            }
        }
        // B tile: fully in-bounds by construction (N%BN==0, K%BK==0)
        *(float4*)&Bs[b_r][b_c] =
            *(const float4*)(B + (long)(k0 + b_r) * ldb + (n0 + b_c));

        __syncthreads();

#pragma unroll
        for (int kk = 0; kk < BK; kk++) {
            float a[TM], b[TN];
            *(float4*)&a[0] = *(float4*)&As[kk][ty * TM];
            *(float4*)&a[4] = *(float4*)&As[kk][ty * TM + 4];
            *(float4*)&b[0] = *(float4*)&Bs[kk][tx * TN];
            *(float4*)&b[4] = *(float4*)&Bs[kk][tx * TN + 4];
#pragma unroll
            for (int i = 0; i < TM; i++)
#pragma unroll
                for (int j = 0; j < TN; j++)
                    acc[i][j] += a[i] * b[j];
        }
        __syncthreads();
    }

#pragma unroll
    for (int i = 0; i < TM; i++) {
        const int gm = m0 + ty * TM + i;
        if (gm >= M) continue;
        float g = 0.f;
        if (EPI == 2) g = gate[(long)gm * gate_ld + gate_idx];
        float* crow = C + (long)gm * ldc + n0 + tx * TN;
#pragma unroll
        for (int j = 0; j < TN; j++) {
            float v = acc[i][j];
            if (EPI == 1) {
                v += bias[n0 + tx * TN + j];
                v = fmaxf(v, 0.f);
            } else if (EPI == 2) {
                v = g * (v + bias[n0 + tx * TN + j]);
                if (!init_flag) v += crow[j];
            }
            crow[j] = v;
        }
    }
}

// out[b, n, 256 + d] = ori[b, n, d]   (float4)
__global__ void concat_ori_kernel(const float* __restrict__ ori,
                                  float* __restrict__ out, int total4)
{
    int idx = blockIdx.x * blockDim.x + threadIdx.x;
    if (idx >= total4) return;
    int d4 = idx & 63;        // 64 float4 per row (256 floats)
    int bn = idx >> 6;        // flattened (b, n)
    float4 v = ((const float4*)ori)[idx];
    ((float4*)(out + (long)bn * 512 + 256))[d4] = v;
}

extern "C" void kernel_launch(void* const* d_in, const int* in_sizes, int n_in,
                              void* d_out, int out_size)
{
    const float* ed  = (const float*)d_in[0];   // [4,8000,5]
    const float* H   = (const float*)d_in[1];   // [4,8000,2000]
    const float* ori = (const float*)d_in[2];   // [4,2000,256]
    const float* W1  = (const float*)d_in[3];   // [5,256,128]
    const float* b1  = (const float*)d_in[4];   // [5,128]
    const float* W2  = (const float*)d_in[5];   // [5,128,256]
    const float* b2  = (const float*)d_in[6];   // [5,256]
    float* out = (float*)d_out;                 // [4,2000,512]

    float *edges, *h, *ef;
    cudaGetSymbolAddress((void**)&edges, g_edges);
    cudaGetSymbolAddress((void**)&h, g_h);
    cudaGetSymbolAddress((void**)&ef, g_ef);

    const int B = 4, E = 8000, Nn = 2000, D = 256, HID = 128, T = 5;

    // 1) edges = H @ ori   (per-batch NN GEMM: M=E, N=D, K=Nn)
    sgemm_kernel<0, false><<<dim3((E + BM - 1) / BM, D / BN, B), 256>>>(
        H, ori, edges, E, D, Nn,
        (long)E * Nn, (long)Nn * D, (long)E * D,
        Nn, D, D, nullptr, nullptr, 0, 0, 0);

    // 2) per-type MLP, gated accumulate into ef (batch folded into M=32000)
    for (int t = 0; t < T; t++) {
        sgemm_kernel<1, false><<<dim3((B * E) / BM, HID / BN, 1), 256>>>(
            edges, W1 + (long)t * D * HID, h, B * E, HID, D,
            0, 0, 0, D, HID, HID, b1 + t * HID, nullptr, 0, 0, 0);
        sgemm_kernel<2, false><<<dim3((B * E) / BM, D / BN, 1), 256>>>(
            h, W2 + (long)t * HID * D, ef, B * E, D, HID,
            0, 0, 0, HID, D, D, b2 + t * D, ed, t, T, (t == 0) ? 1 : 0);
    }

    // 3) out[:, :, :256] = H^T @ ef   (per-batch TN GEMM: M=Nn, N=D, K=E)
    sgemm_kernel<0, true><<<dim3((Nn + BM - 1) / BM, D / BN, B), 256>>>(
        H, ef, out, Nn, D, E,
        (long)E * Nn, (long)E * D, (long)Nn * 2 * D,
        Nn, D, 2 * D, nullptr, nullptr, 0, 0, 0);

    // 4) out[:, :, 256:] = ori
    const int total4 = B * Nn * (D / 4);
    concat_ori_kernel<<<(total4 + 255) / 256, 256>>>(ori, out, total4);
}

// round 2
// speedup vs baseline: 1.4226x; 1.4226x over previous
#include <cuda_runtime.h>
#include <mma.h>

using namespace nvcuda;

// ---------------------------------------------------------------------------
// edge_aggregation: B=4, E=8000, N=2000, D=256, HID=128, T=5
//   edges = H @ ori                                  [B,E,D]
//   for t: h = relu(edges@W1[t]+b1[t]); y = h@W2[t]+b2[t]
//   ef    = sum_t edge_distribution[...,t] * y       [B,E,D]
//   out   = concat(H^T @ ef, ori)                    [B,N,2D]
//
// Round 2: tf32 wmma tensor-core GEMMs (m16n16k8), 128x128x16 tiles,
// double-buffered smem, staged epilogue for partial-M predication.
// ---------------------------------------------------------------------------

__device__ float g_edges[32000 * 256];   // 32.8 MB
__device__ float g_h[32000 * 128];       // 16.4 MB
__device__ float g_ef[32000 * 256];      // 32.8 MB

#define BKK 16

// EPI: 0 = C = acc
//      1 = C = relu(acc + bias[col])
//      2 = C (init ? = : +=) gate[row*gate_ld+gate_idx] * (acc + bias[col])
// TRANS_A: false -> A[M,K] row-major; true -> A[K,M] row-major (use A^T)
// Requires: N % 128 == 0, K % 16 == 0. Partial M handled.
template <int EPI, bool TRANS_A, int BM>
__global__ __launch_bounds__(256, 1)
void gemm_tf32(const float* __restrict__ A, const float* __restrict__ B,
               float* __restrict__ C,
               int M, int N, int K,
               long sA, long sB, long sC,
               int lda, int ldb, int ldc,
               const float* __restrict__ bias,
               const float* __restrict__ gate,
               int gate_idx, int gate_ld, int init_flag)
{
    constexpr int BN   = 128;
    constexpr int WGM  = BM / 32;        // warps along M (4 or 2)
    constexpr int WGN  = 8 / WGM;        // warps along N (2 or 4)
    constexpr int WTN  = BN / WGN;       // warp tile N (64 or 32)
    constexpr int NFR  = WTN / 16;       // N fragments per warp (4 or 2)
    constexpr int AS_LD = BM + 4;
    constexpr int BS_LD = BN + 8;        // 136
    constexpr int ST_LD = WTN + 4;
    constexpr int APASS = BM / 64;       // staging float4s per thread (A)

    constexpr int AS_SZ = 2 * BKK * AS_LD;
    constexpr int BS_SZ = 2 * BKK * BS_LD;
    constexpr int ST_SZ = 8 * 16 * ST_LD;
    constexpr int SMEMF = (AS_SZ + BS_SZ) > ST_SZ ? (AS_SZ + BS_SZ) : ST_SZ;

    __shared__ __align__(16) float smem[SMEMF];
    float* As = smem;              // [2][BKK][AS_LD]
    float* Bs = smem + AS_SZ;      // [2][BKK][BS_LD]

    const int z = blockIdx.z;
    A += (long)z * sA;
    B += (long)z * sB;
    C += (long)z * sC;

    const int m0   = blockIdx.x * BM;
    const int n0   = blockIdx.y * BN;
    const int tid  = threadIdx.x;
    const int warp = tid >> 5;
    const int lane = tid & 31;
    const int wm   = warp % WGM;
    const int wn   = warp / WGM;

    wmma::fragment<wmma::accumulator, 16, 16, 8, float> cf[2][NFR];
#pragma unroll
    for (int i = 0; i < 2; i++)
#pragma unroll
        for (int j = 0; j < NFR; j++)
            wmma::fill_fragment(cf[i][j], 0.0f);

    auto cvt4 = [](float4& v) {
        v.x = wmma::__float_to_tf32(v.x);
        v.y = wmma::__float_to_tf32(v.y);
        v.z = wmma::__float_to_tf32(v.z);
        v.w = wmma::__float_to_tf32(v.w);
    };

    auto load_tile = [&](int it, float4* ra, float4* rb) {
        const int k0 = it * BKK;
        if constexpr (!TRANS_A) {
            const int ak = (tid & 3) * 4;
#pragma unroll
            for (int p = 0; p < APASS; p++) {
                const int gm = m0 + (tid >> 2) + p * 64;
                float4 v = make_float4(0.f, 0.f, 0.f, 0.f);
                if (gm < M) v = *(const float4*)(A + (long)gm * lda + k0 + ak);
                ra[p] = v;
            }
        } else {
            constexpr int TPK = BM / 4;
#pragma unroll
            for (int p = 0; p < APASS; p++) {
                const int k   = tid / TPK + p * (256 / TPK);
                const int gmc = m0 + (tid % TPK) * 4;
                const float* src = A + (long)(k0 + k) * lda + gmc;
                float4 v;
                if (gmc + 3 < M) {
                    v = *(const float4*)src;
                } else {
                    v.x = (gmc + 0 < M) ? src[0] : 0.f;
                    v.y = (gmc + 1 < M) ? src[1] : 0.f;
                    v.z = (gmc + 2 < M) ? src[2] : 0.f;
                    v.w = (gmc + 3 < M) ? src[3] : 0.f;
                }
                ra[p] = v;
            }
        }
        const int bk = tid >> 4;
        const int bn = (tid & 15) * 8;
        const float* bsrc = B + (long)(k0 + bk) * ldb + n0 + bn;
        rb[0] = *(const float4*)bsrc;
        rb[1] = *(const float4*)(bsrc + 4);
#pragma unroll
        for (int p = 0; p < APASS; p++) cvt4(ra[p]);
        cvt4(rb[0]);
        cvt4(rb[1]);
    };

    auto store_tile = [&](int buf, const float4* ra, const float4* rb) {
        float* as = As + buf * BKK * AS_LD;
        float* bs = Bs + buf * BKK * BS_LD;
        if constexpr (!TRANS_A) {
            const int ak = (tid & 3) * 4;
#pragma unroll
            for (int p = 0; p < APASS; p++) {
                const int am = (tid >> 2) + p * 64;
                as[(ak + 0) * AS_LD + am] = ra[p].x;
                as[(ak + 1) * AS_LD + am] = ra[p].y;
                as[(ak + 2) * AS_LD + am] = ra[p].z;
                as[(ak + 3) * AS_LD + am] = ra[p].w;
            }
        } else {
            constexpr int TPK = BM / 4;
#pragma unroll
            for (int p = 0; p < APASS; p++) {
                const int k  = tid / TPK + p * (256 / TPK);
                const int am = (tid % TPK) * 4;
                *(float4*)(as + k * AS_LD + am) = ra[p];
            }
        }
        const int bk = tid >> 4;
        const int bn = (tid & 15) * 8;
        *(float4*)(bs + bk * BS_LD + bn)     = rb[0];
        *(float4*)(bs + bk * BS_LD + bn + 4) = rb[1];
    };

    // prologue
    {
        float4 ra[APASS], rb[2];
        load_tile(0, ra, rb);
        store_tile(0, ra, rb);
    }
    __syncthreads();

    const int niter = K / BKK;
    for (int it = 0; it < niter; it++) {
        const int cur = it & 1;
        const bool hn = (it + 1 < niter);
        float4 ra[APASS], rb[2];
        if (hn) load_tile(it + 1, ra, rb);

        const float* as = As + cur * BKK * AS_LD;
        const float* bs = Bs + cur * BKK * BS_LD;
#pragma unroll
        for (int kk = 0; kk < BKK; kk += 8) {
            wmma::fragment<wmma::matrix_a, 16, 16, 8, wmma::precision::tf32,
                           wmma::col_major> af[2];
            wmma::fragment<wmma::matrix_b, 16, 16, 8, wmma::precision::tf32,
                           wmma::row_major> bf[NFR];
#pragma unroll
            for (int i = 0; i < 2; i++)
                wmma::load_matrix_sync(af[i], as + kk * AS_LD + wm * 32 + i * 16,
                                       AS_LD);
#pragma unroll
            for (int j = 0; j < NFR; j++)
                wmma::load_matrix_sync(bf[j], bs + kk * BS_LD + wn * WTN + j * 16,
                                       BS_LD);
#pragma unroll
            for (int i = 0; i < 2; i++)
#pragma unroll
                for (int j = 0; j < NFR; j++)
                    wmma::mma_sync(cf[i][j], af[i], bf[j], cf[i][j]);
        }
        if (hn) store_tile(cur ^ 1, ra, rb);
        __syncthreads();
    }

    // ---- epilogue via per-warp smem staging (handles partial M) ----
    __syncthreads();   // done with pipeline smem; reuse as stage
    float* stg = smem + warp * (16 * ST_LD);

#pragma unroll
    for (int i = 0; i < 2; i++) {
        if (i == 1) __syncwarp();
#pragma unroll
        for (int j = 0; j < NFR; j++)
            wmma::store_matrix_sync(stg + j * 16, cf[i][j], ST_LD,
                                    wmma::mem_row_major);
        __syncwarp();

        const int r  = lane >> 1;
        const int cb = (lane & 1) * (WTN / 2);
        const int gm = m0 + wm * 32 + i * 16 + r;
        if (gm < M) {
            float g = 0.f;
            if (EPI == 2) g = gate[(long)gm * gate_ld + gate_idx];
            float* crow = C + (long)gm * ldc + n0 + wn * WTN;
            const float* srow = stg + r * ST_LD;
            const int nb = n0 + wn * WTN;
#pragma unroll
            for (int c = cb; c < cb + WTN / 2; c += 4) {
                float4 v = *(const float4*)(srow + c);
                if constexpr (EPI == 1) {
                    float4 bb = *(const float4*)(bias + nb + c);
                    v.x = fmaxf(v.x + bb.x, 0.f);
                    v.y = fmaxf(v.y + bb.y, 0.f);
                    v.z = fmaxf(v.z + bb.z, 0.f);
                    v.w = fmaxf(v.w + bb.w, 0.f);
                } else if constexpr (EPI == 2) {
                    float4 bb = *(const float4*)(bias + nb + c);
                    v.x = g * (v.x + bb.x);
                    v.y = g * (v.y + bb.y);
                    v.z = g * (v.z + bb.z);
                    v.w = g * (v.w + bb.w);
                    if (!init_flag) {
                        float4 o = *(const float4*)(crow + c);
                        v.x += o.x; v.y += o.y; v.z += o.z; v.w += o.w;
                    }
                }
                *(float4*)(crow + c) = v;
            }
        }
    }
}

// out[b, n, 256 + d] = ori[b, n, d]   (float4)
__global__ void concat_ori_kernel(const float* __restrict__ ori,
                                  float* __restrict__ out, int total4)
{
    int idx = blockIdx.x * blockDim.x + threadIdx.x;
    if (idx >= total4) return;
    int d4 = idx & 63;        // 64 float4 per 256-float row
    int bn = idx >> 6;
    float4 v = ((const float4*)ori)[idx];
    ((float4*)(out + (long)bn * 512 + 256))[d4] = v;
}

extern "C" void kernel_launch(void* const* d_in, const int* in_sizes, int n_in,
                              void* d_out, int out_size)
{
    const float* ed  = (const float*)d_in[0];   // [4,8000,5]
    const float* H   = (const float*)d_in[1];   // [4,8000,2000]
    const float* ori = (const float*)d_in[2];   // [4,2000,256]
    const float* W1  = (const float*)d_in[3];   // [5,256,128]
    const float* b1  = (const float*)d_in[4];   // [5,128]
    const float* W2  = (const float*)d_in[5];   // [5,128,256]
    const float* b2  = (const float*)d_in[6];   // [5,256]
    float* out = (float*)d_out;                 // [4,2000,512]

    float *edges, *h, *ef;
    cudaGetSymbolAddress((void**)&edges, g_edges);
    cudaGetSymbolAddress((void**)&h, g_h);
    cudaGetSymbolAddress((void**)&ef, g_ef);

    const int B = 4, E = 8000, Nn = 2000, D = 256, HID = 128, T = 5;

    // 1) edges = H @ ori   (per-batch NN: M=E, N=D, K=Nn)
    gemm_tf32<0, false, 128><<<dim3((E + 127) / 128, D / 128, B), 256>>>(
        H, ori, edges, E, D, Nn,
        (long)E * Nn, (long)Nn * D, (long)E * D,
        Nn, D, D, nullptr, nullptr, 0, 0, 0);

    // 2) per-type MLP, gated accumulate into ef (batch folded: M=32000)
    for (int t = 0; t < T; t++) {
        gemm_tf32<1, false, 128><<<dim3((B * E) / 128, HID / 128, 1), 256>>>(
            edges, W1 + (long)t * D * HID, h, B * E, HID, D,
            0, 0, 0, D, HID, HID, b1 + t * HID, nullptr, 0, 0, 0);
        gemm_tf32<2, false, 128><<<dim3((B * E) / 128, D / 128, 1), 256>>>(
            h, W2 + (long)t * HID * D, ef, B * E, D, HID,
            0, 0, 0, HID, D, D, b2 + t * D, ed, t, T, (t == 0) ? 1 : 0);
    }

    // 3) out[:, :, :256] = H^T @ ef   (per-batch TN: M=Nn, N=D, K=E), BM=64
    gemm_tf32<0, true, 64><<<dim3((Nn + 63) / 64, D / 128, B), 256>>>(
        H, ef, out, Nn, D, E,
        (long)E * Nn, (long)E * D, (long)Nn * 2 * D,
        Nn, D, 2 * D, nullptr, nullptr, 0, 0, 0);

    // 4) out[:, :, 256:] = ori
    const int total4 = B * Nn * (D / 4);
    concat_ori_kernel<<<(total4 + 255) / 256, 256>>>(ori, out, total4);
}

// round 6
// speedup vs baseline: 3.3876x; 2.3813x over previous
#include <cuda_runtime.h>
#include <cstdint>

// ---------------------------------------------------------------------------
// edge_aggregation (B=4, E=8000, N=2000, D=256, HID=128, T=5)
// tf32 mma.sync.m16n8k8 (compute_103-safe), cp.async 3-stage pipeline.
// ALL fp32->tf32 conversions hoisted out of GEMM mainloops:
//   H, ori, W1, W2 converted once; edges/h written as tf32 by epilogues;
//   ef (fp32 accum) converted once before GEMM3.
//   edges = H @ ori                      GEMM1  M=8000 N=256 K=2000  x4
//   h     = relu(edges@W1[t]+b1)         MLP1   M=32000 N=128 K=256  x5
//   ef   += gate_t*(h@W2[t]+b2)          MLP2   M=32000 N=256 K=128  x5
//   out[:, :256] = H^T @ ef              GEMM3  M=2000 N=256 K=8000  (TRANS_A)
//   out[:, 256:] = ori
// ---------------------------------------------------------------------------

__device__ uint32_t g_Ht[4L * 8000 * 2000];   // 256 MB (tf32 bits)
__device__ uint32_t g_orit[4 * 2000 * 256];
__device__ uint32_t g_W1t[5 * 256 * 128];
__device__ uint32_t g_W2t[5 * 128 * 256];
__device__ uint32_t g_edges[32000 * 256];     // tf32, written by GEMM1
__device__ uint32_t g_ht[32000 * 128];        // tf32, written by MLP1
__device__ float    g_ef[32000 * 256];        // fp32 accumulator
__device__ uint32_t g_eft[32000 * 256];       // tf32

// ---------------- PTX helpers ----------------
__device__ __forceinline__ uint32_t smem_u32(const void* p) {
    uint32_t a;
    asm("{ .reg .u64 t; cvta.to.shared.u64 t, %1; cvt.u32.u64 %0, t; }"
        : "=r"(a) : "l"(p));
    return a;
}
__device__ __forceinline__ void cpasync16(uint32_t dst, const void* src, uint32_t sz) {
    asm volatile("cp.async.cg.shared.global [%0], [%1], 16, %2;"
                 :: "r"(dst), "l"(src), "r"(sz) : "memory");
}
#define CP_COMMIT() asm volatile("cp.async.commit_group;" ::: "memory")
#define CP_WAIT1()  asm volatile("cp.async.wait_group 1;" ::: "memory")

__device__ __forceinline__ uint32_t lds32(uint32_t a) {
    uint32_t v;
    asm volatile("ld.shared.b32 %0, [%1];" : "=r"(v) : "r"(a));
    return v;
}
__device__ __forceinline__ uint32_t f2tf32(float x) {
    uint32_t r;
    asm("cvt.rna.tf32.f32 %0, %1;" : "=r"(r) : "f"(x));
    return r;
}
__device__ __forceinline__ void mma_tf32(float (&c)[4], const uint32_t (&a)[4],
                                         uint32_t b0, uint32_t b1) {
    asm volatile(
        "mma.sync.aligned.m16n8k8.row.col.f32.tf32.tf32.f32 "
        "{%0,%1,%2,%3}, {%4,%5,%6,%7}, {%8,%9}, {%0,%1,%2,%3};"
        : "+f"(c[0]), "+f"(c[1]), "+f"(c[2]), "+f"(c[3])
        : "r"(a[0]), "r"(a[1]), "r"(a[2]), "r"(a[3]), "r"(b0), "r"(b1));
}

// ---------------------------------------------------------------------------
// Tile 128x128, K-chunk 32, 512 threads (16 warps: 4M x 4N, 32x32 per warp).
// Smem (per stage):
//   A non-trans: [128 m][36 w]  (144 B rows)  = 18432 B
//   A trans    : [32 k][136 w]  (544 B rows)  = 17408 B
//   B          : [32 k][136 w]  (544 B rows)  = 17408 B
// 3-stage cp.async. EPI 0: C=acc | 1: relu(acc+bias) | 2: gate*(acc+bias) accum
// TRANS_A: A memory is [K,M] row-major. Requires N%128==0, M%4==0, niter>=2.
// ---------------------------------------------------------------------------
template <int EPI, bool TRANS_A, bool OUT_TF32>
__global__ __launch_bounds__(512, 1)
void gemm_tf32(const uint32_t* __restrict__ A, const uint32_t* __restrict__ Bm,
               void* __restrict__ Cv, int M, int N, int K,
               long sA, long sB, long sC, int lda, int ldb, int ldc,
               const float* __restrict__ bias, const float* __restrict__ gate,
               int gidx, int gld, int init_flag)
{
    constexpr int AS_BYTES = TRANS_A ? 32 * 544 : 128 * 144;
    constexpr int BS_BYTES = 32 * 544;

    extern __shared__ __align__(16) char dyn[];
    const uint32_t as0 = smem_u32(dyn);
    const uint32_t bs0 = as0 + 3 * AS_BYTES;

    const int tid = threadIdx.x;
    const int warp = tid >> 5, lane = tid & 31;
    const int wm = warp & 3, wn = warp >> 2;
    const int m_w = wm * 32, n_w = wn * 32;
    const int g = lane >> 2, t = lane & 3;

    const int z = blockIdx.z;
    A += (long)z * sA;  Bm += (long)z * sB;
    const long m0 = (long)blockIdx.x * 128;
    const int  n0 = blockIdx.y * 128;

    const int niter = (K + 31) / 32;

    float acc[2][4][4];
#pragma unroll
    for (int a = 0; a < 2; a++)
#pragma unroll
        for (int b = 0; b < 4; b++)
#pragma unroll
            for (int c = 0; c < 4; c++) acc[a][b][c] = 0.f;

    auto issue = [&](int it, int stage) {
        const long k0 = (long)it * 32;
        if constexpr (!TRANS_A) {
            // A: 128 rows x 8 f4; 2 passes of 64 rows
#pragma unroll
            for (int p = 0; p < 2; p++) {
                const int row = (tid >> 3) + p * 64;
                const int c4 = tid & 7;
                const long gm = m0 + row, gk = k0 + c4 * 4;
                const uint32_t ok = (gm < M && gk < K);
                const uint32_t* src = A + (ok ? gm * (long)lda + gk : 0);
                cpasync16(as0 + stage * AS_BYTES + row * 144 + c4 * 16,
                          src, ok ? 16u : 0u);
            }
        } else {
            // A: 32 k-rows x 32 f4 (m); 2 passes of 16 f4
#pragma unroll
            for (int p = 0; p < 2; p++) {
                const int kr = tid >> 4;
                const int m4 = (tid & 15) + p * 16;
                const long gk = k0 + kr, gm = m0 + m4 * 4;
                const uint32_t ok = (gk < K && gm < M);
                const uint32_t* src = A + (ok ? gk * (long)lda + gm : 0);
                cpasync16(as0 + stage * AS_BYTES + kr * 544 + m4 * 16,
                          src, ok ? 16u : 0u);
            }
        }
        // B: 32 k-rows x 32 f4 (n); 2 passes
#pragma unroll
        for (int p = 0; p < 2; p++) {
            const int kr = tid >> 4;
            const int c4 = (tid & 15) + p * 16;
            const long gk = k0 + kr;
            const uint32_t ok = (gk < K);
            const uint32_t* src = Bm + (ok ? gk * (long)ldb : 0) + n0 + c4 * 4;
            cpasync16(bs0 + stage * BS_BYTES + kr * 544 + c4 * 16,
                      src, ok ? 16u : 0u);
        }
        CP_COMMIT();
    };

    auto compute = [&](int stage) {
        const uint32_t as = as0 + stage * AS_BYTES;
        const uint32_t bs = bs0 + stage * BS_BYTES;
#pragma unroll
        for (int ks = 0; ks < 32; ks += 8) {
            uint32_t a[2][4], b[4][2];
            if constexpr (!TRANS_A) {
                const uint32_t base = as + (m_w + g) * 144 + (ks + t) * 4;
#pragma unroll
                for (int mt = 0; mt < 2; mt++) {
                    const uint32_t ab = base + mt * (16 * 144);
                    a[mt][0] = lds32(ab);
                    a[mt][1] = lds32(ab + 8 * 144);
                    a[mt][2] = lds32(ab + 16);
                    a[mt][3] = lds32(ab + 8 * 144 + 16);
                }
            } else {
                const uint32_t base = as + (ks + t) * 544 + (m_w + g) * 4;
#pragma unroll
                for (int mt = 0; mt < 2; mt++) {
                    const uint32_t ab = base + mt * 64;
                    a[mt][0] = lds32(ab);
                    a[mt][1] = lds32(ab + 32);
                    a[mt][2] = lds32(ab + 4 * 544);
                    a[mt][3] = lds32(ab + 4 * 544 + 32);
                }
            }
            {
                const uint32_t base = bs + (ks + t) * 544 + (n_w + g) * 4;
#pragma unroll
                for (int nt = 0; nt < 4; nt++) {
                    b[nt][0] = lds32(base + nt * 32);
                    b[nt][1] = lds32(base + nt * 32 + 4 * 544);
                }
            }
#pragma unroll
            for (int mt = 0; mt < 2; mt++)
#pragma unroll
                for (int nt = 0; nt < 4; nt++)
                    mma_tf32(acc[mt][nt], a[mt], b[nt][0], b[nt][1]);
        }
    };

    // prologue (all uses have niter >= 2)
    issue(0, 0);
    issue(1, 1);

    for (int it = 0; it < niter; it++) {
        CP_WAIT1();
        __syncthreads();
        if (it + 2 < niter) issue(it + 2, (it + 2) % 3);
        compute(it % 3);
    }

    // ---------------- epilogue ----------------
    const int tg = t * 2;
#pragma unroll
    for (int mt = 0; mt < 2; mt++) {
#pragma unroll
        for (int h = 0; h < 2; h++) {
            const long r = m0 + m_w + mt * 16 + g + h * 8;
            if (r >= M) continue;
            float gt = 0.f;
            if (EPI == 2) gt = gate[r * (long)gld + gidx];
#pragma unroll
            for (int nt = 0; nt < 4; nt++) {
                const int col = n_w + nt * 8 + tg;   // within [0,128)
                float v0 = acc[mt][nt][h * 2 + 0];
                float v1 = acc[mt][nt][h * 2 + 1];
                if (EPI == 1) {
                    float2 bb = *(const float2*)(bias + n0 + col);
                    v0 = fmaxf(v0 + bb.x, 0.f);
                    v1 = fmaxf(v1 + bb.y, 0.f);
                } else if (EPI == 2) {
                    float2 bb = *(const float2*)(bias + n0 + col);
                    v0 = gt * (v0 + bb.x);
                    v1 = gt * (v1 + bb.y);
                }
                if constexpr (OUT_TF32) {
                    uint32_t* p = (uint32_t*)Cv + z * sC + r * (long)ldc + n0 + col;
                    uint2 o;
                    o.x = f2tf32(v0);
                    o.y = f2tf32(v1);
                    *reinterpret_cast<uint2*>(p) = o;
                } else {
                    float* p = (float*)Cv + z * sC + r * (long)ldc + n0 + col;
                    if (EPI == 2 && !init_flag) {
                        float2 o = *(const float2*)p;
                        v0 += o.x; v1 += o.y;
                    }
                    *reinterpret_cast<float2*>(p) = make_float2(v0, v1);
                }
            }
        }
    }
}

// ---------------------------------------------------------------------------
__global__ void f32_to_tf32_kernel(const float* __restrict__ src,
                                   uint32_t* __restrict__ dst, long n4)
{
    const long i = (long)blockIdx.x * blockDim.x + threadIdx.x;
    if (i >= n4) return;
    float4 v = ((const float4*)src)[i];
    uint4 o;
    o.x = f2tf32(v.x);
    o.y = f2tf32(v.y);
    o.z = f2tf32(v.z);
    o.w = f2tf32(v.w);
    ((uint4*)dst)[i] = o;
}

// out[b,n,256:512] = ori[b,n,:]
__global__ void concat_ori_kernel(const float* __restrict__ ori,
                                  float* __restrict__ out, int total4)
{
    int idx = blockIdx.x * blockDim.x + threadIdx.x;
    if (idx >= total4) return;
    int d4 = idx & 63;
    int bn = idx >> 6;
    float4 v = ((const float4*)ori)[idx];
    ((float4*)(out + (long)bn * 512 + 256))[d4] = v;
}

// ---------------------------------------------------------------------------
extern "C" void kernel_launch(void* const* d_in, const int* in_sizes, int n_in,
                              void* d_out, int out_size)
{
    const float* ed  = (const float*)d_in[0];   // [4,8000,5]
    const float* H   = (const float*)d_in[1];   // [4,8000,2000]
    const float* ori = (const float*)d_in[2];   // [4,2000,256]
    const float* W1  = (const float*)d_in[3];   // [5,256,128]
    const float* b1  = (const float*)d_in[4];   // [5,128]
    const float* W2  = (const float*)d_in[5];   // [5,128,256]
    const float* b2  = (const float*)d_in[6];   // [5,256]
    float* out = (float*)d_out;                 // [4,2000,512]

    uint32_t *Ht, *orit, *W1t, *W2t, *edges, *ht, *eft;
    float* ef;
    cudaGetSymbolAddress((void**)&Ht, g_Ht);
    cudaGetSymbolAddress((void**)&orit, g_orit);
    cudaGetSymbolAddress((void**)&W1t, g_W1t);
    cudaGetSymbolAddress((void**)&W2t, g_W2t);
    cudaGetSymbolAddress((void**)&edges, g_edges);
    cudaGetSymbolAddress((void**)&ht, g_ht);
    cudaGetSymbolAddress((void**)&ef, g_ef);
    cudaGetSymbolAddress((void**)&eft, g_eft);

    const int SM_NT = 3 * (128 * 144 + 32 * 544);   // 107520
    const int SM_T  = 3 * (32 * 544 + 32 * 544);    // 104448
    cudaFuncSetAttribute(gemm_tf32<0, false, true>,
                         cudaFuncAttributeMaxDynamicSharedMemorySize, SM_NT);
    cudaFuncSetAttribute(gemm_tf32<1, false, true>,
                         cudaFuncAttributeMaxDynamicSharedMemorySize, SM_NT);
    cudaFuncSetAttribute(gemm_tf32<2, false, false>,
                         cudaFuncAttributeMaxDynamicSharedMemorySize, SM_NT);
    cudaFuncSetAttribute(gemm_tf32<0, true, false>,
                         cudaFuncAttributeMaxDynamicSharedMemorySize, SM_T);

    // 0) convert operands to tf32 (rna) once
    {
        long n4;
        n4 = 4L * 8000 * 2000 / 4;
        f32_to_tf32_kernel<<<(unsigned)((n4 + 255) / 256), 256>>>(H, Ht, n4);
        n4 = 4L * 2000 * 256 / 4;
        f32_to_tf32_kernel<<<(unsigned)((n4 + 255) / 256), 256>>>(ori, orit, n4);
        n4 = 5L * 256 * 128 / 4;
        f32_to_tf32_kernel<<<(unsigned)((n4 + 255) / 256), 256>>>(W1, W1t, n4);
        n4 = 5L * 128 * 256 / 4;
        f32_to_tf32_kernel<<<(unsigned)((n4 + 255) / 256), 256>>>(W2, W2t, n4);
    }

    // 1) edges = H @ ori (tf32 out)
    gemm_tf32<0, false, true><<<dim3(63, 2, 4), 512, SM_NT>>>(
        Ht, orit, edges, 8000, 256, 2000,
        8000L * 2000, 2000L * 256, 8000L * 256,
        2000, 256, 256, nullptr, nullptr, 0, 0, 0);

    // 2) per-type MLP (M = 32000 folded)
    for (int t = 0; t < 5; t++) {
        gemm_tf32<1, false, true><<<dim3(250, 1, 1), 512, SM_NT>>>(
            edges, W1t + (long)t * 256 * 128, ht, 32000, 128, 256,
            0, 0, 0, 256, 128, 128, b1 + t * 128, nullptr, 0, 0, 0);
        gemm_tf32<2, false, false><<<dim3(250, 2, 1), 512, SM_NT>>>(
            ht, W2t + (long)t * 128 * 256, ef, 32000, 256, 128,
            0, 0, 0, 128, 256, 256, b2 + t * 256, ed, t, 5, (t == 0) ? 1 : 0);
    }

    // 3) ef -> tf32
    {
        const long n4 = 32000L * 256 / 4;
        f32_to_tf32_kernel<<<(unsigned)((n4 + 255) / 256), 256>>>(ef, eft, n4);
    }

    // 4) out[:, :, :256] = H^T @ ef  (A = H as [K,M], TRANS_A)
    gemm_tf32<0, true, false><<<dim3(16, 2, 4), 512, SM_T>>>(
        Ht, eft, out, 2000, 256, 8000,
        8000L * 2000, 8000L * 256, 2000L * 512,
        2000, 256, 512, nullptr, nullptr, 0, 0, 0);

    // 5) out[:, :, 256:] = ori
    concat_ori_kernel<<<(4 * 2000 * 64 + 255) / 256, 256>>>(ori, out, 4 * 2000 * 64);
}